// round 16
// baseline (speedup 1.0000x reference)
#include <cuda_runtime.h>

// Problem constants (fixed by setup_inputs)
#define NF 1000
#define NB 2049
#define EPSV 1.1920928955078125e-07f   // float32 eps
#define SQEPS 3.45266983e-04f          // sqrt(eps)

#define WARPS 8
#define KF 14                  // f-values per thread per phase
#define FPT (WARPS * KF)       // 112 f per tile
#define NBX 65                 // ceil(2049/32)
#define NTY 9                  // ceil(1000/112)
#define NBLK (NBX * NTY)       // 585 blocks; <= 592 resident @ 4 blocks/SM

typedef unsigned long long u64;

// Accumulators (no cudaMalloc allowed). Zero-initialized at module load.
__device__ float4 g_acc1[NB * 4];
__device__ float4 g_acc2[NB * 4];

// Per-b-column barrier state (one padded counter per bx group).
__device__ unsigned g_bar1[NBX * 32];
__device__ unsigned g_bar2[NBX * 32];
__device__ unsigned g_fin [NBX * 32];

__device__ __forceinline__ void cp16(float4* dst, const float4* src, int sz) {
    unsigned d = (unsigned)__cvta_generic_to_shared(dst);
    asm volatile("cp.async.cg.shared.global [%0], [%1], 16, %2;"
                 :: "r"(d), "l"(src), "r"(sz) : "memory");
}
#define CP_COMMIT() asm volatile("cp.async.commit_group;" ::: "memory")
#define CP_WAIT2()  asm volatile("cp.async.wait_group 2;" ::: "memory")
#define CP_WAIT3()  asm volatile("cp.async.wait_group 3;" ::: "memory")
#define CP_WAIT0()  asm volatile("cp.async.wait_group 0;" ::: "memory")

// Packed f32x2 ops (sm_103a; ptxas will not auto-generate these from C++)
#define FMA2(d,a,b,c) asm("fma.rn.f32x2 %0, %1, %2, %3;" : "=l"(d) : "l"(a), "l"(b), "l"(c))
#define MUL2(d,a,b)   asm("mul.rn.f32x2 %0, %1, %2;"     : "=l"(d) : "l"(a), "l"(b))
#define ADD2(d,a,b)   asm("add.rn.f32x2 %0, %1, %2;"     : "=l"(d) : "l"(a), "l"(b))
#define NEG2(d,a)     asm("xor.b64 %0, %1, 0x8000000080000000;" : "=l"(d) : "l"(a))
#define UNPK2(lo,hi,p) asm("mov.b64 {%0, %1}, %2;" : "=f"(lo), "=f"(hi) : "l"(p))
#define BCAST2(d,f_)  asm("mov.b64 %0, {%1, %1};" : "=l"(d) : "f"(f_))
#define PACK2(d,a,b)  asm("mov.b64 %0, {%1, %2};" : "=l"(d) : "f"(a), "f"(b))

// Group barrier: NTY arrivals on this group's counter.
__device__ __forceinline__ void group_barrier(unsigned* cnt) {
    __syncthreads();
    __threadfence();
    if (threadIdx.x == 0 && threadIdx.y == 0) {
        atomicAdd(cnt, 1u);
        while (atomicAdd(cnt, 0u) < (unsigned)NTY) __nanosleep(32);
    }
    __syncthreads();
    __threadfence();
}

__device__ __forceinline__ float4 norm_acc(float4 a) {
    float inv = 1.0f / (EPSV + 0.5f * (a.x + a.y));
    return make_float4(a.x * inv, a.y * inv, a.z * inv, a.w * inv);
}

// Swizzled float4 slot inside a 32-row x 4-component warp tile.
__device__ __forceinline__ int slot_of(int bl, int c) {
    return bl * 4 + ((c + (bl >> 1)) & 3);
}

// Phase A: issue one warp-tile (f, B0..B0+31) of y as 4 coalesced cp.async rounds.
__device__ __forceinline__ void issue_tile(const float4* __restrict__ y,
                                           int f, int B0, int lane, float4* st)
{
    const float4* base = y + ((size_t)(f < NF ? f : 0) * NB + B0) * 4;
#pragma unroll
    for (int r = 0; r < 4; r++) {
        int j = r * 32 + lane;
        int bl = j >> 2, c = j & 3;
        int ok = (f < NF && (B0 + bl) < NB) ? 16 : 0;   // OOB -> zero-fill
        cp16(st + slot_of(bl, c), base + j, ok);
    }
    CP_COMMIT();
}

// Phases B/C: stage (vout, x) row f. Lane-private slots: st[lane] = v, st[32+lane] = x.
__device__ __forceinline__ void issue_vx(const float4* __restrict__ v,
                                         const float4* __restrict__ xx,
                                         int f, int B0, int lane, float4* st)
{
    bool fok = (f >= 0 && f < NF);
    size_t row = (size_t)(fok ? f : 0) * NB + B0;
    int ok = (fok && (B0 + lane) < NB) ? 16 : 0;        // OOB -> zero-fill
    cp16(st + lane,      v  + row + lane, ok);
    cp16(st + 32 + lane, xx + row + lane, ok);
    CP_COMMIT();
}

// Block reduction over threadIdx.y (8 warps) + atomics into acc.
__device__ __forceinline__ void block_reduce_atomic(
    const float a00[4], const float a11[4], const float are[4], const float aim[4],
    int b, bool bok, float4* acc, float (*red)[32][17])
{
    int lane = threadIdx.x, ty = threadIdx.y;
    float* p = red[ty][lane];
#pragma unroll
    for (int s = 0; s < 4; s++) {
        p[s]      = a00[s];
        p[4 + s]  = a11[s];
        p[8 + s]  = are[s];
        p[12 + s] = aim[s];
    }
    __syncthreads();
#pragma unroll
    for (int st = WARPS / 2; st >= 1; st >>= 1) {
        if (ty < st) {
            float* q = red[ty + st][lane];
#pragma unroll
            for (int i = 0; i < 16; i++) p[i] += q[i];
        }
        __syncthreads();
    }
    if (ty == 0 && bok) {
#pragma unroll
        for (int s = 0; s < 4; s++) {
            float* dst = ((float*)acc) + (b * 4 + s) * 4;
            atomicAdd(dst + 0, p[s]);
            atomicAdd(dst + 1, p[4 + s]);
            atomicAdd(dst + 2, p[8 + s]);
            atomicAdd(dst + 3, p[12 + s]);
        }
    }
    __syncthreads();
}

// Packed Wiener step shared by phases B and C.
struct PackedRn {
    u64 X[2], Y[2], Z[2], W[2];   // {Rn[2p].c, Rn[2p+1].c} per component
};

__device__ __forceinline__ void wiener_packed(
    const PackedRn& R, ulonglong2 vvp, float4 xv,
    u64 o0r[2], u64 o0i[2], u64 o1r[2], u64 o1i[2])
{
    u64 vp[2] = {vvp.x, vvp.y};
    // Cxx components via packed pair partial sums + horizontal add
    u64 pc; float lo, hi;
    MUL2(pc, vp[0], R.X[0]); FMA2(pc, vp[1], R.X[1], pc); UNPK2(lo, hi, pc);
    float c00 = SQEPS + lo + hi;
    MUL2(pc, vp[0], R.Y[0]); FMA2(pc, vp[1], R.Y[1], pc); UNPK2(lo, hi, pc);
    float c11 = SQEPS + lo + hi;
    MUL2(pc, vp[0], R.Z[0]); FMA2(pc, vp[1], R.Z[1], pc); UNPK2(lo, hi, pc);
    float cre = lo + hi;
    MUL2(pc, vp[0], R.W[0]); FMA2(pc, vp[1], R.W[1], pc); UNPK2(lo, hi, pc);
    float cim = lo + hi;

    float det = c00 * c11 - (cre * cre + cim * cim);
    float id = 1.0f / det;
    float w0r = id * (c11 * xv.x - (cre * xv.z - cim * xv.w));
    float w0i = id * (c11 * xv.y - (cre * xv.w + cim * xv.z));
    float w1r = id * (c00 * xv.z - (cre * xv.x + cim * xv.y));
    float w1i = id * (c00 * xv.w - (cre * xv.y - cim * xv.x));

    u64 pw0r, pw0i, pw1r, pw1i, pnw0r, pnw1i;
    BCAST2(pw0r, w0r); BCAST2(pw0i, w0i);
    BCAST2(pw1r, w1r); BCAST2(pw1i, w1i);
    BCAST2(pnw0r, -w0r); BCAST2(pnw1i, -w1i);

#pragma unroll
    for (int p = 0; p < 2; p++) {
        u64 t;
        MUL2(t, R.X[p], pw0r); FMA2(t, R.Z[p], pw1r, t); FMA2(t, R.W[p], pnw1i, t);
        MUL2(o0r[p], vp[p], t);
        MUL2(t, R.X[p], pw0i); FMA2(t, R.Z[p], pw1i, t); FMA2(t, R.W[p], pw1r, t);
        MUL2(o0i[p], vp[p], t);
        MUL2(t, R.Z[p], pw0r); FMA2(t, R.W[p], pw0i, t); FMA2(t, R.Y[p], pw1r, t);
        MUL2(o1r[p], vp[p], t);
        MUL2(t, R.Z[p], pw0i); FMA2(t, R.W[p], pnw0r, t); FMA2(t, R.Y[p], pw1i, t);
        MUL2(o1i[p], vp[p], t);
    }
}

__device__ __forceinline__ PackedRn make_packed_rn(const float4* acc, int bc) {
    float4 Rf[4];
#pragma unroll
    for (int s = 0; s < 4; s++) Rf[s] = norm_acc(acc[bc * 4 + s]);
    PackedRn R;
#pragma unroll
    for (int p = 0; p < 2; p++) {
        PACK2(R.X[p], Rf[2*p].x, Rf[2*p+1].x);
        PACK2(R.Y[p], Rf[2*p].y, Rf[2*p+1].y);
        PACK2(R.Z[p], Rf[2*p].z, Rf[2*p+1].z);
        PACK2(R.W[p], Rf[2*p].w, Rf[2*p+1].w);
    }
    return R;
}

__global__ void __launch_bounds__(256, 4) k_fused(
    const float4* __restrict__ y,
    const float4* __restrict__ x,
    float4* __restrict__ vout,
    float4* __restrict__ yout,
    float* __restrict__ rout)
{
    // Per-warp 384-float4 region (6 KB). Phase A: 3 stages x 128.
    // Phases B/C: 4 stages x 64 (vx staging) at [0..255] + transpose at [256..383].
    // Reduction buffer (17 KB) overlays the whole thing between phases.
    __shared__ float4 sm[WARPS][384];
    float (*red)[32][17] = (float(*)[32][17])(&sm[0][0]);

    int lane = threadIdx.x, ty = threadIdx.y;
    int tid = ty * 32 + lane;
    int bx = blockIdx.x;
    int B0 = bx * 32;
    int b = B0 + lane;
    bool bok = b < NB;
    int bc = bok ? b : 0;
    int f0 = blockIdx.y * FPT + ty;      // warp-uniform f base
    float4* stg = &sm[ty][0];

    unsigned* bar1 = &g_bar1[bx * 32];
    unsigned* bar2 = &g_bar2[bx * 32];
    unsigned* fin  = &g_fin [bx * 32];

    // Reset this group's g_acc2 slice (before our barrier-1 arrival).
    if (blockIdx.y == 0 && tid < 128) {
        g_acc2[bx * 128 + tid] = make_float4(0.f, 0.f, 0.f, 0.f);
    }

    u64 halfp;
    asm("mov.b64 %0, {%1, %1};" : "=l"(halfp) : "f"(0.5f));

    // ====== Phase A: reduce y y^H stats over f AND emit v1 into vout ==========
    // Accumulation in packed f32x2: component pairs (s0,s1) and (s2,s3).
    {
        u64 pa00[2] = {0, 0}, pa11[2] = {0, 0}, pare[2] = {0, 0}, paim[2] = {0, 0};

        issue_tile(y, f0 + 0 * WARPS, B0, lane, stg + 0 * 128);
        issue_tile(y, f0 + 1 * WARPS, B0, lane, stg + 1 * 128);
        issue_tile(y, f0 + 2 * WARPS, B0, lane, stg + 2 * 128);
#pragma unroll
        for (int k = 0; k < KF; k++) {
            CP_WAIT2();
            __syncwarp();
            float4* s = stg + (k % 3) * 128;
            // float4 = two packed f32x2 halves: .x=(s0,s1), .y=(s2,s3)
            ulonglong2 q0 = *(const ulonglong2*)&s[slot_of(lane, 0)];  // c0r
            ulonglong2 q1 = *(const ulonglong2*)&s[slot_of(lane, 1)];  // c0i
            ulonglong2 q2 = *(const ulonglong2*)&s[slot_of(lane, 2)];  // c1r
            ulonglong2 q3 = *(const ulonglong2*)&s[slot_of(lane, 3)];  // c1i
            __syncwarp();   // all lanes done reading stage k%3 before re-fill below
            issue_tile(y, f0 + (k + 3) * WARPS, B0, lane, stg + ((k + 3) % 3) * 128);

            u64 n0a, n0b;
            NEG2(n0a, q0.x); NEG2(n0b, q0.y);
            u64 t00a, t00b, t11a, t11b;
            MUL2(t00a, q0.x, q0.x); FMA2(t00a, q1.x, q1.x, t00a);   // |c0|^2
            MUL2(t00b, q0.y, q0.y); FMA2(t00b, q1.y, q1.y, t00b);
            MUL2(t11a, q2.x, q2.x); FMA2(t11a, q3.x, q3.x, t11a);   // |c1|^2
            MUL2(t11b, q2.y, q2.y); FMA2(t11b, q3.y, q3.y, t11b);
            ADD2(pa00[0], pa00[0], t00a); ADD2(pa00[1], pa00[1], t00b);
            ADD2(pa11[0], pa11[0], t11a); ADD2(pa11[1], pa11[1], t11b);
            FMA2(pare[0], q0.x, q2.x, pare[0]); FMA2(pare[0], q1.x, q3.x, pare[0]); // Re c0 c1*
            FMA2(pare[1], q0.y, q2.y, pare[1]); FMA2(pare[1], q1.y, q3.y, pare[1]);
            FMA2(paim[0], q1.x, q2.x, paim[0]); FMA2(paim[0], n0a, q3.x, paim[0]); // Im c0 c1*
            FMA2(paim[1], q1.y, q2.y, paim[1]); FMA2(paim[1], n0b, q3.y, paim[1]);

            u64 v1a, v1b;
            ADD2(v1a, t00a, t11a); MUL2(v1a, v1a, halfp);
            ADD2(v1b, t00b, t11b); MUL2(v1b, v1b, halfp);

            int f = f0 + k * WARPS;
            if (bok && f < NF) {  // regular 128-bit store -> stays in L2 for phase B
                ulonglong2 vw; vw.x = v1a; vw.y = v1b;
                *(ulonglong2*)(vout + (size_t)f * NB + b) = vw;
            }
        }
        CP_WAIT0();

        float a00[4], a11[4], are[4], aim[4];
        UNPK2(a00[0], a00[1], pa00[0]); UNPK2(a00[2], a00[3], pa00[1]);
        UNPK2(a11[0], a11[1], pa11[0]); UNPK2(a11[2], a11[3], pa11[1]);
        UNPK2(are[0], are[1], pare[0]); UNPK2(are[2], are[3], pare[1]);
        UNPK2(aim[0], aim[1], paim[0]); UNPK2(aim[2], aim[3], paim[1]);

        __syncthreads();   // staging -> red overlay handoff (cross-warp)
        block_reduce_atomic(a00, a11, are, aim, b, bok, g_acc1, red);
    }
    group_barrier(bar1);   // only the NTY blocks sharing bx

    // ====== Phase B: rebuild yc1 from (v1, R1, x); accumulate R2; v2 -> vout ===
    // Loads pipelined via lane-private depth-4 cp.async staging; packed math.
    // All issues strictly AFTER the barrier (pre-barrier vout read-back raced
    // in-flight stores in R13 and regressed badly).
    {
        u64 pa00[2] = {0, 0}, pa11[2] = {0, 0}, pare[2] = {0, 0}, paim[2] = {0, 0};
        PackedRn R = make_packed_rn(g_acc1, bc);

        issue_vx(vout, x, f0 + (KF - 1) * WARPS, B0, lane, stg + ((KF - 1) % 4) * 64);
        issue_vx(vout, x, f0 + (KF - 2) * WARPS, B0, lane, stg + ((KF - 2) % 4) * 64);
        issue_vx(vout, x, f0 + (KF - 3) * WARPS, B0, lane, stg + ((KF - 3) % 4) * 64);
        issue_vx(vout, x, f0 + (KF - 4) * WARPS, B0, lane, stg + ((KF - 4) % 4) * 64);
#pragma unroll
        for (int k = KF - 1; k >= 0; k--) {     // reverse: freshest v1 lines first
            CP_WAIT3();
            float4* s = stg + (k % 4) * 64;
            ulonglong2 vvp = *(const ulonglong2*)&s[lane];   // lane-private
            float4 xv = s[32 + lane];
            issue_vx(vout, x, f0 + (k - 4) * WARPS, B0, lane, s);   // same slot, dist 4

            u64 o0r[2], o0i[2], o1r[2], o1i[2];
            wiener_packed(R, vvp, xv, o0r, o0i, o1r, o1i);

            // Stats + v2 (OOB lanes: v=0, x=0 -> all zero; accumulating is exact)
            ulonglong2 vw;
#pragma unroll
            for (int p = 0; p < 2; p++) {
                u64 t00, t11, no0r;
                MUL2(t00, o0r[p], o0r[p]); FMA2(t00, o0i[p], o0i[p], t00);
                MUL2(t11, o1r[p], o1r[p]); FMA2(t11, o1i[p], o1i[p], t11);
                ADD2(pa00[p], pa00[p], t00);
                ADD2(pa11[p], pa11[p], t11);
                FMA2(pare[p], o0r[p], o1r[p], pare[p]);
                FMA2(pare[p], o0i[p], o1i[p], pare[p]);
                FMA2(paim[p], o0i[p], o1r[p], paim[p]);
                NEG2(no0r, o0r[p]);
                FMA2(paim[p], no0r, o1i[p], paim[p]);
                u64 pv2;
                ADD2(pv2, t00, t11); MUL2(pv2, pv2, halfp);
                if (p == 0) vw.x = pv2; else vw.y = pv2;
            }
            int f = f0 + k * WARPS;
            if (bok && f < NF)   // overwrite v1 with v2; stays in L2 for phase C
                *(ulonglong2*)(vout + (size_t)f * NB + b) = vw;
        }
        CP_WAIT0();       // drain zero-fill stragglers before red overlay reuse

        float a00[4], a11[4], are[4], aim[4];
        UNPK2(a00[0], a00[1], pa00[0]); UNPK2(a00[2], a00[3], pa00[1]);
        UNPK2(a11[0], a11[1], pa11[0]); UNPK2(a11[2], a11[3], pa11[1]);
        UNPK2(are[0], are[1], pare[0]); UNPK2(are[2], are[3], pare[1]);
        UNPK2(aim[0], aim[1], paim[0]); UNPK2(aim[2], aim[3], paim[1]);

        __syncthreads();
        block_reduce_atomic(a00, a11, are, aim, b, bok, g_acc2, red);
    }
    group_barrier(bar2);

    // ====== Phase C: iter-2 filter from (v2, x) [L2-hot], coalesced y_out ======
    {
        PackedRn R = make_packed_rn(g_acc2, bc);

        if (blockIdx.y == 0 && ty == 0 && bok) {   // emit R_out (B, C, C, 2, S)
#pragma unroll
            for (int s = 0; s < 4; s++) {
                float4 Rf = norm_acc(g_acc2[bc * 4 + s]);
                float* p = rout + b * 32 + s;
                p[0]  = Rf.x;  p[4]  = 0.f;        // R[0,0]
                p[8]  = Rf.z;  p[12] = Rf.w;       // R[0,1]
                p[16] = Rf.z;  p[20] = -Rf.w;      // R[1,0] = conj
                p[24] = Rf.y;  p[28] = 0.f;        // R[1,1]
            }
        }

        float4* sp = stg + 256;   // transpose buffer (disjoint from staging 0..255)
        issue_vx(vout, x, f0 + 0 * WARPS, B0, lane, stg + 0 * 64);
        issue_vx(vout, x, f0 + 1 * WARPS, B0, lane, stg + 1 * 64);
        issue_vx(vout, x, f0 + 2 * WARPS, B0, lane, stg + 2 * 64);
        issue_vx(vout, x, f0 + 3 * WARPS, B0, lane, stg + 3 * 64);
#pragma unroll
        for (int k = 0; k < KF; k++) {
            int f = f0 + k * WARPS;
            bool fok = f < NF;                        // warp-uniform
            CP_WAIT3();
            float4* s = stg + (k % 4) * 64;
            ulonglong2 vvp = *(const ulonglong2*)&s[lane];
            float4 xv = s[32 + lane];
            issue_vx(vout, x, f0 + (k + 4) * WARPS, B0, lane, s);

            u64 o0r[2], o0i[2], o1r[2], o1i[2];
            wiener_packed(R, vvp, xv, o0r, o0i, o1r, o1i);

            if (fok) {   // warp-uniform: smem transpose -> coalesced STG
                __syncwarp();
                ulonglong2 w;
                w.x = o0r[0]; w.y = o0r[1]; *(ulonglong2*)&sp[slot_of(lane, 0)] = w;
                w.x = o0i[0]; w.y = o0i[1]; *(ulonglong2*)&sp[slot_of(lane, 1)] = w;
                w.x = o1r[0]; w.y = o1r[1]; *(ulonglong2*)&sp[slot_of(lane, 2)] = w;
                w.x = o1i[0]; w.y = o1i[1]; *(ulonglong2*)&sp[slot_of(lane, 3)] = w;
                __syncwarp();
                float4* base = yout + ((size_t)f * NB + B0) * 4;
#pragma unroll
                for (int r = 0; r < 4; r++) {
                    int j = r * 32 + lane;
                    int bl = j >> 2, c = j & 3;
                    if (B0 + bl < NB)
                        __stcs(base + j, sp[slot_of(bl, c)]);
                }
            }
        }
        CP_WAIT0();   // drain stragglers before exit
    }

    // Reset this group's g_acc1 slice for the next replay.
    if (blockIdx.y == 0 && tid < 128) {
        g_acc1[bx * 128 + tid] = make_float4(0.f, 0.f, 0.f, 0.f);
    }

    // Last of the NTY group blocks out resets the group's barrier counters.
    if (tid == 0) {
        __threadfence();
        if (atomicAdd(fin, 1u) == (unsigned)(NTY - 1)) {
            *bar1 = 0; *bar2 = 0; *fin = 0;
            __threadfence();
        }
    }
}

extern "C" void kernel_launch(void* const* d_in, const int* in_sizes, int n_in,
                              void* d_out, int out_size)
{
    const float4* y = (const float4*)d_in[0];
    const float4* x = (const float4*)d_in[1];
    float* out = (float*)d_out;

    float4* yout = (float4*)out;                                     // (F,B,C,2,S)
    float4* vout = (float4*)(out + (size_t)NF * NB * 16);            // (F,B,S)
    float*  rout = out + (size_t)NF * NB * 16 + (size_t)NF * NB * 4; // (B,C,C,2,S)

    dim3 blk(32, WARPS);
    dim3 grd(NBX, NTY);
    k_fused<<<grd, blk>>>(y, x, vout, yout, rout);
}

// round 17
// speedup vs baseline: 1.0528x; 1.0528x over previous
#include <cuda_runtime.h>

// Problem constants (fixed by setup_inputs)
#define NF 1000
#define NB 2049
#define EPSV 1.1920928955078125e-07f   // float32 eps
#define SQEPS 3.45266983e-04f          // sqrt(eps)

#define WARPS 8
#define KF 14                  // f-values per thread per phase
#define FPT (WARPS * KF)       // 112 f per tile
#define NBX 65                 // ceil(2049/32)
#define NTY 9                  // ceil(1000/112)
#define NBLK (NBX * NTY)       // 585 blocks; <= 592 resident @ 4 blocks/SM

typedef unsigned long long u64;

// Accumulators (no cudaMalloc allowed). Zero-initialized at module load.
__device__ float4 g_acc1[NB * 4];
__device__ float4 g_acc2[NB * 4];

// Per-b-column barrier state (one padded counter per bx group).
__device__ unsigned g_bar1[NBX * 32];
__device__ unsigned g_bar2[NBX * 32];
__device__ unsigned g_fin [NBX * 32];

// Plain 16B async copy (normal L2 priority)
__device__ __forceinline__ void cp16(float4* dst, const float4* src, int sz) {
    unsigned d = (unsigned)__cvta_generic_to_shared(dst);
    asm volatile("cp.async.cg.shared.global [%0], [%1], 16, %2;"
                 :: "r"(d), "l"(src), "r"(sz) : "memory");
}
// 16B async copy with L2 evict-first hint (for once-used streams)
__device__ __forceinline__ void cp16_ef(float4* dst, const float4* src, int sz, u64 pol) {
    unsigned d = (unsigned)__cvta_generic_to_shared(dst);
    asm volatile("cp.async.cg.shared.global.L2::cache_hint [%0], [%1], 16, %2, %3;"
                 :: "r"(d), "l"(src), "r"(sz), "l"(pol) : "memory");
}
__device__ __forceinline__ u64 make_evict_first_policy() {
    u64 pol;
    asm("createpolicy.fractional.L2::evict_first.b64 %0, 1.0;" : "=l"(pol));
    return pol;
}
#define CP_COMMIT() asm volatile("cp.async.commit_group;" ::: "memory")
#define CP_WAIT2()  asm volatile("cp.async.wait_group 2;" ::: "memory")
#define CP_WAIT0()  asm volatile("cp.async.wait_group 0;" ::: "memory")

// Packed f32x2 ops (sm_103a; ptxas will not auto-generate these from C++)
#define FMA2(d,a,b,c) asm("fma.rn.f32x2 %0, %1, %2, %3;" : "=l"(d) : "l"(a), "l"(b), "l"(c))
#define MUL2(d,a,b)   asm("mul.rn.f32x2 %0, %1, %2;"     : "=l"(d) : "l"(a), "l"(b))
#define ADD2(d,a,b)   asm("add.rn.f32x2 %0, %1, %2;"     : "=l"(d) : "l"(a), "l"(b))
#define NEG2(d,a)     asm("xor.b64 %0, %1, 0x8000000080000000;" : "=l"(d) : "l"(a))
#define UNPK2(lo,hi,p) asm("mov.b64 {%0, %1}, %2;" : "=f"(lo), "=f"(hi) : "l"(p))
#define BCAST2(d,f_)  asm("mov.b64 %0, {%1, %1};" : "=l"(d) : "f"(f_))
#define PACK2(d,a,b)  asm("mov.b64 %0, {%1, %2};" : "=l"(d) : "f"(a), "f"(b))

// Group barrier: NTY arrivals on this group's counter.
__device__ __forceinline__ void group_barrier(unsigned* cnt) {
    __syncthreads();
    __threadfence();
    if (threadIdx.x == 0 && threadIdx.y == 0) {
        atomicAdd(cnt, 1u);
        while (atomicAdd(cnt, 0u) < (unsigned)NTY) __nanosleep(32);
    }
    __syncthreads();
    __threadfence();
}

__device__ __forceinline__ float4 norm_acc(float4 a) {
    float inv = 1.0f / (EPSV + 0.5f * (a.x + a.y));
    return make_float4(a.x * inv, a.y * inv, a.z * inv, a.w * inv);
}

// Swizzled float4 slot inside a 32-row x 4-component warp tile.
__device__ __forceinline__ int slot_of(int bl, int c) {
    return bl * 4 + ((c + (bl >> 1)) & 3);
}

// Phase A: issue one warp-tile (f, B0..B0+31) of y as 4 coalesced cp.async rounds.
// y is used exactly once -> evict-first so it doesn't displace v1/x in L2.
__device__ __forceinline__ void issue_tile(const float4* __restrict__ y,
                                           int f, int B0, int lane, float4* st, u64 pol)
{
    const float4* base = y + ((size_t)(f < NF ? f : 0) * NB + B0) * 4;
#pragma unroll
    for (int r = 0; r < 4; r++) {
        int j = r * 32 + lane;
        int bl = j >> 2, c = j & 3;
        int ok = (f < NF && (B0 + bl) < NB) ? 16 : 0;   // OOB -> zero-fill
        cp16_ef(st + slot_of(bl, c), base + j, ok, pol);
    }
    CP_COMMIT();
}

// Phases B/C: stage (vout, x) row f. Lane-private slots: st[lane] = v, st[32+lane] = x.
// ef=false (phase B): v1 lines are overwritten in place right after -> keep resident.
// ef=true (phase C): last use of both v2 and x -> evict-first.
__device__ __forceinline__ void issue_vx(const float4* __restrict__ v,
                                         const float4* __restrict__ xx,
                                         int f, int B0, int lane, float4* st,
                                         bool ef, u64 pol)
{
    bool fok = (f >= 0 && f < NF);
    size_t row = (size_t)(fok ? f : 0) * NB + B0;
    int ok = (fok && (B0 + lane) < NB) ? 16 : 0;        // OOB -> zero-fill
    if (ef) {
        cp16_ef(st + lane,      v  + row + lane, ok, pol);
        cp16_ef(st + 32 + lane, xx + row + lane, ok, pol);
    } else {
        cp16(st + lane,      v  + row + lane, ok);
        cp16(st + 32 + lane, xx + row + lane, ok);
    }
    CP_COMMIT();
}

// Block reduction over threadIdx.y (8 warps) + atomics into acc.
__device__ __forceinline__ void block_reduce_atomic(
    const float a00[4], const float a11[4], const float are[4], const float aim[4],
    int b, bool bok, float4* acc, float (*red)[32][17])
{
    int lane = threadIdx.x, ty = threadIdx.y;
    float* p = red[ty][lane];
#pragma unroll
    for (int s = 0; s < 4; s++) {
        p[s]      = a00[s];
        p[4 + s]  = a11[s];
        p[8 + s]  = are[s];
        p[12 + s] = aim[s];
    }
    __syncthreads();
#pragma unroll
    for (int st = WARPS / 2; st >= 1; st >>= 1) {
        if (ty < st) {
            float* q = red[ty + st][lane];
#pragma unroll
            for (int i = 0; i < 16; i++) p[i] += q[i];
        }
        __syncthreads();
    }
    if (ty == 0 && bok) {
#pragma unroll
        for (int s = 0; s < 4; s++) {
            float* dst = ((float*)acc) + (b * 4 + s) * 4;
            atomicAdd(dst + 0, p[s]);
            atomicAdd(dst + 1, p[4 + s]);
            atomicAdd(dst + 2, p[8 + s]);
            atomicAdd(dst + 3, p[12 + s]);
        }
    }
    __syncthreads();
}

// Packed Wiener step shared by phases B and C.
struct PackedRn {
    u64 X[2], Y[2], Z[2], W[2];   // {Rn[2p].c, Rn[2p+1].c} per component
};

__device__ __forceinline__ void wiener_packed(
    const PackedRn& R, ulonglong2 vvp, float4 xv,
    u64 o0r[2], u64 o0i[2], u64 o1r[2], u64 o1i[2])
{
    u64 vp[2] = {vvp.x, vvp.y};
    // Cxx components via packed pair partial sums + horizontal add
    u64 pc; float lo, hi;
    MUL2(pc, vp[0], R.X[0]); FMA2(pc, vp[1], R.X[1], pc); UNPK2(lo, hi, pc);
    float c00 = SQEPS + lo + hi;
    MUL2(pc, vp[0], R.Y[0]); FMA2(pc, vp[1], R.Y[1], pc); UNPK2(lo, hi, pc);
    float c11 = SQEPS + lo + hi;
    MUL2(pc, vp[0], R.Z[0]); FMA2(pc, vp[1], R.Z[1], pc); UNPK2(lo, hi, pc);
    float cre = lo + hi;
    MUL2(pc, vp[0], R.W[0]); FMA2(pc, vp[1], R.W[1], pc); UNPK2(lo, hi, pc);
    float cim = lo + hi;

    float det = c00 * c11 - (cre * cre + cim * cim);
    float id = 1.0f / det;
    float w0r = id * (c11 * xv.x - (cre * xv.z - cim * xv.w));
    float w0i = id * (c11 * xv.y - (cre * xv.w + cim * xv.z));
    float w1r = id * (c00 * xv.z - (cre * xv.x + cim * xv.y));
    float w1i = id * (c00 * xv.w - (cre * xv.y - cim * xv.x));

    u64 pw0r, pw0i, pw1r, pw1i, pnw0r, pnw1i;
    BCAST2(pw0r, w0r); BCAST2(pw0i, w0i);
    BCAST2(pw1r, w1r); BCAST2(pw1i, w1i);
    BCAST2(pnw0r, -w0r); BCAST2(pnw1i, -w1i);

#pragma unroll
    for (int p = 0; p < 2; p++) {
        u64 t;
        MUL2(t, R.X[p], pw0r); FMA2(t, R.Z[p], pw1r, t); FMA2(t, R.W[p], pnw1i, t);
        MUL2(o0r[p], vp[p], t);
        MUL2(t, R.X[p], pw0i); FMA2(t, R.Z[p], pw1i, t); FMA2(t, R.W[p], pw1r, t);
        MUL2(o0i[p], vp[p], t);
        MUL2(t, R.Z[p], pw0r); FMA2(t, R.W[p], pw0i, t); FMA2(t, R.Y[p], pw1r, t);
        MUL2(o1r[p], vp[p], t);
        MUL2(t, R.Z[p], pw0i); FMA2(t, R.W[p], pnw0r, t); FMA2(t, R.Y[p], pw1i, t);
        MUL2(o1i[p], vp[p], t);
    }
}

__device__ __forceinline__ PackedRn make_packed_rn(const float4* acc, int bc) {
    float4 Rf[4];
#pragma unroll
    for (int s = 0; s < 4; s++) Rf[s] = norm_acc(acc[bc * 4 + s]);
    PackedRn R;
#pragma unroll
    for (int p = 0; p < 2; p++) {
        PACK2(R.X[p], Rf[2*p].x, Rf[2*p+1].x);
        PACK2(R.Y[p], Rf[2*p].y, Rf[2*p+1].y);
        PACK2(R.Z[p], Rf[2*p].z, Rf[2*p+1].z);
        PACK2(R.W[p], Rf[2*p].w, Rf[2*p+1].w);
    }
    return R;
}

__global__ void __launch_bounds__(256, 4) k_fused(
    const float4* __restrict__ y,
    const float4* __restrict__ x,
    float4* __restrict__ vout,
    float4* __restrict__ yout,
    float* __restrict__ rout)
{
    // Per-warp 384-float4 region (6 KB). Phase A: 3 stages x 128.
    // Phases B/C: 3 stages x 64 (vx staging) at [0..191] + transpose at [192..319].
    // Reduction buffer (17 KB) overlays the whole thing between phases.
    __shared__ float4 sm[WARPS][384];
    float (*red)[32][17] = (float(*)[32][17])(&sm[0][0]);

    int lane = threadIdx.x, ty = threadIdx.y;
    int tid = ty * 32 + lane;
    int bx = blockIdx.x;
    int B0 = bx * 32;
    int b = B0 + lane;
    bool bok = b < NB;
    int bc = bok ? b : 0;
    int f0 = blockIdx.y * FPT + ty;      // warp-uniform f base
    float4* stg = &sm[ty][0];

    unsigned* bar1 = &g_bar1[bx * 32];
    unsigned* bar2 = &g_bar2[bx * 32];
    unsigned* fin  = &g_fin [bx * 32];

    u64 polEF = make_evict_first_policy();

    // Reset this group's g_acc2 slice (before our barrier-1 arrival).
    if (blockIdx.y == 0 && tid < 128) {
        g_acc2[bx * 128 + tid] = make_float4(0.f, 0.f, 0.f, 0.f);
    }

    u64 halfp;
    asm("mov.b64 %0, {%1, %1};" : "=l"(halfp) : "f"(0.5f));

    // ====== Phase A: reduce y y^H stats over f AND emit v1 into vout ==========
    // Accumulation in packed f32x2: component pairs (s0,s1) and (s2,s3).
    {
        u64 pa00[2] = {0, 0}, pa11[2] = {0, 0}, pare[2] = {0, 0}, paim[2] = {0, 0};

        issue_tile(y, f0 + 0 * WARPS, B0, lane, stg + 0 * 128, polEF);
        issue_tile(y, f0 + 1 * WARPS, B0, lane, stg + 1 * 128, polEF);
        issue_tile(y, f0 + 2 * WARPS, B0, lane, stg + 2 * 128, polEF);
#pragma unroll
        for (int k = 0; k < KF; k++) {
            CP_WAIT2();
            __syncwarp();
            float4* s = stg + (k % 3) * 128;
            // float4 = two packed f32x2 halves: .x=(s0,s1), .y=(s2,s3)
            ulonglong2 q0 = *(const ulonglong2*)&s[slot_of(lane, 0)];  // c0r
            ulonglong2 q1 = *(const ulonglong2*)&s[slot_of(lane, 1)];  // c0i
            ulonglong2 q2 = *(const ulonglong2*)&s[slot_of(lane, 2)];  // c1r
            ulonglong2 q3 = *(const ulonglong2*)&s[slot_of(lane, 3)];  // c1i
            __syncwarp();   // all lanes done reading stage k%3 before re-fill below
            issue_tile(y, f0 + (k + 3) * WARPS, B0, lane, stg + ((k + 3) % 3) * 128, polEF);

            u64 n0a, n0b;
            NEG2(n0a, q0.x); NEG2(n0b, q0.y);
            u64 t00a, t00b, t11a, t11b;
            MUL2(t00a, q0.x, q0.x); FMA2(t00a, q1.x, q1.x, t00a);   // |c0|^2
            MUL2(t00b, q0.y, q0.y); FMA2(t00b, q1.y, q1.y, t00b);
            MUL2(t11a, q2.x, q2.x); FMA2(t11a, q3.x, q3.x, t11a);   // |c1|^2
            MUL2(t11b, q2.y, q2.y); FMA2(t11b, q3.y, q3.y, t11b);
            ADD2(pa00[0], pa00[0], t00a); ADD2(pa00[1], pa00[1], t00b);
            ADD2(pa11[0], pa11[0], t11a); ADD2(pa11[1], pa11[1], t11b);
            FMA2(pare[0], q0.x, q2.x, pare[0]); FMA2(pare[0], q1.x, q3.x, pare[0]); // Re c0 c1*
            FMA2(pare[1], q0.y, q2.y, pare[1]); FMA2(pare[1], q1.y, q3.y, pare[1]);
            FMA2(paim[0], q1.x, q2.x, paim[0]); FMA2(paim[0], n0a, q3.x, paim[0]); // Im c0 c1*
            FMA2(paim[1], q1.y, q2.y, paim[1]); FMA2(paim[1], n0b, q3.y, paim[1]);

            u64 v1a, v1b;
            ADD2(v1a, t00a, t11a); MUL2(v1a, v1a, halfp);
            ADD2(v1b, t00b, t11b); MUL2(v1b, v1b, halfp);

            int f = f0 + k * WARPS;
            if (bok && f < NF) {  // regular 128-bit store -> stays in L2 for phase B
                ulonglong2 vw; vw.x = v1a; vw.y = v1b;
                *(ulonglong2*)(vout + (size_t)f * NB + b) = vw;
            }
        }
        CP_WAIT0();

        float a00[4], a11[4], are[4], aim[4];
        UNPK2(a00[0], a00[1], pa00[0]); UNPK2(a00[2], a00[3], pa00[1]);
        UNPK2(a11[0], a11[1], pa11[0]); UNPK2(a11[2], a11[3], pa11[1]);
        UNPK2(are[0], are[1], pare[0]); UNPK2(are[2], are[3], pare[1]);
        UNPK2(aim[0], aim[1], paim[0]); UNPK2(aim[2], aim[3], paim[1]);

        __syncthreads();   // staging -> red overlay handoff (cross-warp)
        block_reduce_atomic(a00, a11, are, aim, b, bok, g_acc1, red);
    }
    group_barrier(bar1);   // only the NTY blocks sharing bx

    // ====== Phase B: rebuild yc1 from (v1, R1, x); accumulate R2; v2 -> vout ===
    // Loads pipelined via lane-private depth-3 cp.async staging; packed math.
    {
        u64 pa00[2] = {0, 0}, pa11[2] = {0, 0}, pare[2] = {0, 0}, paim[2] = {0, 0};
        PackedRn R = make_packed_rn(g_acc1, bc);

        issue_vx(vout, x, f0 + (KF - 1) * WARPS, B0, lane, stg + ((KF - 1) % 3) * 64, false, polEF);
        issue_vx(vout, x, f0 + (KF - 2) * WARPS, B0, lane, stg + ((KF - 2) % 3) * 64, false, polEF);
        issue_vx(vout, x, f0 + (KF - 3) * WARPS, B0, lane, stg + ((KF - 3) % 3) * 64, false, polEF);
#pragma unroll
        for (int k = KF - 1; k >= 0; k--) {     // reverse: freshest v1 lines first
            CP_WAIT2();
            float4* s = stg + (k % 3) * 64;
            ulonglong2 vvp = *(const ulonglong2*)&s[lane];   // lane-private
            float4 xv = s[32 + lane];
            issue_vx(vout, x, f0 + (k - 3) * WARPS, B0, lane, s, false, polEF);

            u64 o0r[2], o0i[2], o1r[2], o1i[2];
            wiener_packed(R, vvp, xv, o0r, o0i, o1r, o1i);

            // Stats + v2 (OOB lanes: v=0, x=0 -> all zero; accumulating is exact)
            ulonglong2 vw;
#pragma unroll
            for (int p = 0; p < 2; p++) {
                u64 t00, t11, no0r;
                MUL2(t00, o0r[p], o0r[p]); FMA2(t00, o0i[p], o0i[p], t00);
                MUL2(t11, o1r[p], o1r[p]); FMA2(t11, o1i[p], o1i[p], t11);
                ADD2(pa00[p], pa00[p], t00);
                ADD2(pa11[p], pa11[p], t11);
                FMA2(pare[p], o0r[p], o1r[p], pare[p]);
                FMA2(pare[p], o0i[p], o1i[p], pare[p]);
                FMA2(paim[p], o0i[p], o1r[p], paim[p]);
                NEG2(no0r, o0r[p]);
                FMA2(paim[p], no0r, o1i[p], paim[p]);
                u64 pv2;
                ADD2(pv2, t00, t11); MUL2(pv2, pv2, halfp);
                if (p == 0) vw.x = pv2; else vw.y = pv2;
            }
            int f = f0 + k * WARPS;
            if (bok && f < NF)   // overwrite v1 with v2; stays in L2 for phase C
                *(ulonglong2*)(vout + (size_t)f * NB + b) = vw;
        }
        CP_WAIT0();       // drain zero-fill stragglers before red overlay reuse

        float a00[4], a11[4], are[4], aim[4];
        UNPK2(a00[0], a00[1], pa00[0]); UNPK2(a00[2], a00[3], pa00[1]);
        UNPK2(a11[0], a11[1], pa11[0]); UNPK2(a11[2], a11[3], pa11[1]);
        UNPK2(are[0], are[1], pare[0]); UNPK2(are[2], are[3], pare[1]);
        UNPK2(aim[0], aim[1], paim[0]); UNPK2(aim[2], aim[3], paim[1]);

        __syncthreads();
        block_reduce_atomic(a00, a11, are, aim, b, bok, g_acc2, red);
    }
    group_barrier(bar2);

    // ====== Phase C: iter-2 filter from (v2, x) [L2-hot], coalesced y_out ======
    {
        PackedRn R = make_packed_rn(g_acc2, bc);

        if (blockIdx.y == 0 && ty == 0 && bok) {   // emit R_out (B, C, C, 2, S)
#pragma unroll
            for (int s = 0; s < 4; s++) {
                float4 Rf = norm_acc(g_acc2[bc * 4 + s]);
                float* p = rout + b * 32 + s;
                p[0]  = Rf.x;  p[4]  = 0.f;        // R[0,0]
                p[8]  = Rf.z;  p[12] = Rf.w;       // R[0,1]
                p[16] = Rf.z;  p[20] = -Rf.w;      // R[1,0] = conj
                p[24] = Rf.y;  p[28] = 0.f;        // R[1,1]
            }
        }

        float4* sp = stg + 192;   // transpose buffer (disjoint from vx staging 0..191)
        issue_vx(vout, x, f0 + 0 * WARPS, B0, lane, stg + 0 * 64, true, polEF);
        issue_vx(vout, x, f0 + 1 * WARPS, B0, lane, stg + 1 * 64, true, polEF);
        issue_vx(vout, x, f0 + 2 * WARPS, B0, lane, stg + 2 * 64, true, polEF);
#pragma unroll
        for (int k = 0; k < KF; k++) {
            int f = f0 + k * WARPS;
            bool fok = f < NF;                        // warp-uniform
            CP_WAIT2();
            float4* s = stg + (k % 3) * 64;
            ulonglong2 vvp = *(const ulonglong2*)&s[lane];
            float4 xv = s[32 + lane];
            issue_vx(vout, x, f0 + (k + 3) * WARPS, B0, lane, s, true, polEF);

            u64 o0r[2], o0i[2], o1r[2], o1i[2];
            wiener_packed(R, vvp, xv, o0r, o0i, o1r, o1i);

            if (fok) {   // warp-uniform: smem transpose -> coalesced STG
                __syncwarp();
                ulonglong2 w;
                w.x = o0r[0]; w.y = o0r[1]; *(ulonglong2*)&sp[slot_of(lane, 0)] = w;
                w.x = o0i[0]; w.y = o0i[1]; *(ulonglong2*)&sp[slot_of(lane, 1)] = w;
                w.x = o1r[0]; w.y = o1r[1]; *(ulonglong2*)&sp[slot_of(lane, 2)] = w;
                w.x = o1i[0]; w.y = o1i[1]; *(ulonglong2*)&sp[slot_of(lane, 3)] = w;
                __syncwarp();
                float4* base = yout + ((size_t)f * NB + B0) * 4;
#pragma unroll
                for (int r = 0; r < 4; r++) {
                    int j = r * 32 + lane;
                    int bl = j >> 2, c = j & 3;
                    if (B0 + bl < NB)
                        __stcs(base + j, sp[slot_of(bl, c)]);
                }
            }
        }
        CP_WAIT0();   // drain stragglers before exit
    }

    // Reset this group's g_acc1 slice for the next replay.
    if (blockIdx.y == 0 && tid < 128) {
        g_acc1[bx * 128 + tid] = make_float4(0.f, 0.f, 0.f, 0.f);
    }

    // Last of the NTY group blocks out resets the group's barrier counters.
    if (tid == 0) {
        __threadfence();
        if (atomicAdd(fin, 1u) == (unsigned)(NTY - 1)) {
            *bar1 = 0; *bar2 = 0; *fin = 0;
            __threadfence();
        }
    }
}

extern "C" void kernel_launch(void* const* d_in, const int* in_sizes, int n_in,
                              void* d_out, int out_size)
{
    const float4* y = (const float4*)d_in[0];
    const float4* x = (const float4*)d_in[1];
    float* out = (float*)d_out;

    float4* yout = (float4*)out;                                     // (F,B,C,2,S)
    float4* vout = (float4*)(out + (size_t)NF * NB * 16);            // (F,B,S)
    float*  rout = out + (size_t)NF * NB * 16 + (size_t)NF * NB * 4; // (B,C,C,2,S)

    dim3 blk(32, WARPS);
    dim3 grd(NBX, NTY);
    k_fused<<<grd, blk>>>(y, x, vout, yout, rout);
}